// round 1
// baseline (speedup 1.0000x reference)
#include <cuda_runtime.h>
#include <cuda_bf16.h>

// Contrastive loss:
//   per pair p: a = emb[pair_a[p]], b = emb[pair_b[p]]  (rows of D=512 floats)
//   sq = ||a||^2 + ||b||^2 - 2 a.b ; d = sqrt(max(sq,1e-12))
//   loss_p = (1-i)*max(0, m-d)^2 + i*d^2,  m = 1.0
//   out = sum_p loss_p / (P + 1e-10)
//
// Strategy: warp-per-pair float4 gather (128B coalesced, 8 independent LDGs
// per lane -> MLP=8), shuffle reduce, block partials to a __device__ array,
// deterministic second-kernel tree reduction (no float atomics).

#define D_DIM 512
#define VEC_PER_ROW (D_DIM / 4)      // 128 float4 per row
#define WARPS_PER_BLOCK 8
#define THREADS_PER_BLOCK (WARPS_PER_BLOCK * 32)
#define MAX_BLOCKS 16384

__device__ float g_partials[MAX_BLOCKS];

__global__ __launch_bounds__(THREADS_PER_BLOCK)
void contrastive_pair_kernel(const float* __restrict__ emb,
                             const int* __restrict__ pair_a,
                             const int* __restrict__ pair_b,
                             const int* __restrict__ pair_same,
                             int P)
{
    const int warp_id = threadIdx.x >> 5;
    const int lane    = threadIdx.x & 31;
    const int p       = blockIdx.x * WARPS_PER_BLOCK + warp_id;

    float loss = 0.0f;

    if (p < P) {
        const int ia = pair_a[p];
        const int ib = pair_b[p];
        const float4* __restrict__ ra =
            reinterpret_cast<const float4*>(emb) + (size_t)ia * VEC_PER_ROW;
        const float4* __restrict__ rb =
            reinterpret_cast<const float4*>(emb) + (size_t)ib * VEC_PER_ROW;

        float saa = 0.0f, sbb = 0.0f, sab = 0.0f;

        // 128 float4 per row / 32 lanes = 4 iterations; issue all 8 loads
        // per iteration independently (a[k] and b[k]).
        float4 va[4], vb[4];
        #pragma unroll
        for (int k = 0; k < 4; ++k) {
            va[k] = __ldg(ra + lane + k * 32);
            vb[k] = __ldg(rb + lane + k * 32);
        }
        #pragma unroll
        for (int k = 0; k < 4; ++k) {
            saa += va[k].x * va[k].x + va[k].y * va[k].y
                 + va[k].z * va[k].z + va[k].w * va[k].w;
            sbb += vb[k].x * vb[k].x + vb[k].y * vb[k].y
                 + vb[k].z * vb[k].z + vb[k].w * vb[k].w;
            sab += va[k].x * vb[k].x + va[k].y * vb[k].y
                 + va[k].z * vb[k].z + va[k].w * vb[k].w;
        }

        // Warp tree reduction of the three sums.
        #pragma unroll
        for (int off = 16; off > 0; off >>= 1) {
            saa += __shfl_xor_sync(0xFFFFFFFFu, saa, off);
            sbb += __shfl_xor_sync(0xFFFFFFFFu, sbb, off);
            sab += __shfl_xor_sync(0xFFFFFFFFu, sab, off);
        }

        if (lane == 0) {
            float sq = saa + sbb - 2.0f * sab;
            sq = fmaxf(sq, 1e-12f);
            float d = sqrtf(sq);
            float i = (float)pair_same[p];
            float h = fmaxf(0.0f, 1.0f - d);
            loss = (1.0f - i) * h * h + i * d * d;
        }
    }

    // Block reduction of per-warp losses (lane 0 of each warp holds one).
    __shared__ float s_loss[WARPS_PER_BLOCK];
    if (lane == 0) s_loss[warp_id] = loss;
    __syncthreads();

    if (threadIdx.x == 0) {
        float acc = 0.0f;
        #pragma unroll
        for (int w = 0; w < WARPS_PER_BLOCK; ++w) acc += s_loss[w];
        g_partials[blockIdx.x] = acc;
    }
}

__global__ void contrastive_reduce_kernel(float* __restrict__ out,
                                          int num_blocks, int P)
{
    __shared__ float s[256];
    float acc = 0.0f;
    for (int i = threadIdx.x; i < num_blocks; i += 256)
        acc += g_partials[i];
    s[threadIdx.x] = acc;
    __syncthreads();
    #pragma unroll
    for (int off = 128; off > 0; off >>= 1) {
        if (threadIdx.x < off) s[threadIdx.x] += s[threadIdx.x + off];
        __syncthreads();
    }
    if (threadIdx.x == 0)
        out[0] = s[0] / ((float)P + 1e-10f);
}

extern "C" void kernel_launch(void* const* d_in, const int* in_sizes, int n_in,
                              void* d_out, int out_size)
{
    const float* emb       = (const float*)d_in[0];
    const int*   pair_a    = (const int*)d_in[1];
    const int*   pair_b    = (const int*)d_in[2];
    const int*   pair_same = (const int*)d_in[3];
    float*       out       = (float*)d_out;

    const int P = in_sizes[1];  // element count of pair_a
    int num_blocks = (P + WARPS_PER_BLOCK - 1) / WARPS_PER_BLOCK;
    if (num_blocks > MAX_BLOCKS) num_blocks = MAX_BLOCKS;  // safety (P=32768 -> 4096)

    contrastive_pair_kernel<<<num_blocks, THREADS_PER_BLOCK>>>(
        emb, pair_a, pair_b, pair_same, P);
    contrastive_reduce_kernel<<<1, 256>>>(out, num_blocks, P);
}